// round 1
// baseline (speedup 1.0000x reference)
#include <cuda_runtime.h>
#include <math.h>

#define B_ 2
#define S_ 2048
#define E_ 1024
#define H_ 16
#define D_ 64
#define BH_ (B_*H_)

// Scratch (allocation-free rule: device globals)
__device__ float g_Q[(size_t)BH_ * S_ * D_];
__device__ float g_K[(size_t)BH_ * S_ * D_];
__device__ float g_V[(size_t)BH_ * S_ * D_];
__device__ float g_C[(size_t)BH_ * S_ * D_];

// ---------------------------------------------------------------------------
// QKV projection: Out[b,h,s,d] = sum_e X[b,s,e] * W[h,e,d] + bias[h,d]
// GEMM tile 128(M=s) x 64(N=d full) x 16(K=e chunk), 256 threads, 8x4/thread.
// grid = (S/128, B*H, 3)  z: 0=q,1=k,2=v
// ---------------------------------------------------------------------------
__global__ __launch_bounds__(256) void proj_kernel(
    const float* __restrict__ q, const float* __restrict__ k, const float* __restrict__ v,
    const float* __restrict__ Wq, const float* __restrict__ Wk, const float* __restrict__ Wv,
    const float* __restrict__ bq, const float* __restrict__ bk, const float* __restrict__ bv)
{
    __shared__ float As[16][132];   // A transposed: As[kk][m], padded stride 132
    __shared__ float Bs[16][64];    // Bs[kk][n]

    const int z = blockIdx.z;
    const float* X    = (z == 0) ? q  : (z == 1) ? k  : v;
    const float* W    = (z == 0) ? Wq : (z == 1) ? Wk : Wv;
    const float* bias = (z == 0) ? bq : (z == 1) ? bk : bv;
    float* Out        = (z == 0) ? g_Q : (z == 1) ? g_K : g_V;

    const int bh = blockIdx.y;
    const int b = bh >> 4;
    const int h = bh & 15;
    const int s0 = blockIdx.x * 128;
    const int tid = threadIdx.x;
    const int ng = tid & 15;   // n-group: 4 cols
    const int mg = tid >> 4;   // m-group: 8 rows

    const float* Xb = X + ((size_t)b * S_ + s0) * E_;
    const float* Wh = W + (size_t)h * E_ * D_;

    float acc[8][4];
#pragma unroll
    for (int i = 0; i < 8; i++)
#pragma unroll
        for (int j = 0; j < 4; j++) acc[i][j] = 0.f;

    for (int k0 = 0; k0 < E_; k0 += 16) {
        // load A tile 128x16, store transposed
#pragma unroll
        for (int it = 0; it < 2; it++) {
            int i   = tid + it * 256;       // 0..511 float4 slots
            int row = i >> 2;               // 0..127
            int c4  = (i & 3) * 4;          // 0,4,8,12
            float4 f = *(const float4*)(Xb + (size_t)row * E_ + k0 + c4);
            As[c4 + 0][row] = f.x; As[c4 + 1][row] = f.y;
            As[c4 + 2][row] = f.z; As[c4 + 3][row] = f.w;
        }
        // load B tile 16x64
        {
            int r  = tid >> 4;
            int c4 = (tid & 15) * 4;
            *(float4*)&Bs[r][c4] = *(const float4*)(Wh + (size_t)(k0 + r) * D_ + c4);
        }
        __syncthreads();
#pragma unroll
        for (int kk = 0; kk < 16; kk++) {
            float4 a0 = *(float4*)&As[kk][mg * 8];
            float4 a1 = *(float4*)&As[kk][mg * 8 + 4];
            float4 b4 = *(float4*)&Bs[kk][ng * 4];
            float a[8] = {a0.x, a0.y, a0.z, a0.w, a1.x, a1.y, a1.z, a1.w};
            float bb[4] = {b4.x, b4.y, b4.z, b4.w};
#pragma unroll
            for (int i = 0; i < 8; i++)
#pragma unroll
                for (int j = 0; j < 4; j++) acc[i][j] += a[i] * bb[j];
        }
        __syncthreads();
    }

    float4 bias4 = *(const float4*)(bias + h * D_ + ng * 4);
    float* Ob = Out + ((size_t)bh * S_ + s0 + mg * 8) * D_ + ng * 4;
#pragma unroll
    for (int i = 0; i < 8; i++) {
        float4 r;
        r.x = acc[i][0] + bias4.x; r.y = acc[i][1] + bias4.y;
        r.z = acc[i][2] + bias4.z; r.w = acc[i][3] + bias4.w;
        *(float4*)(Ob + (size_t)i * D_) = r;
    }
}

// ---------------------------------------------------------------------------
// Flash attention (fp32, online softmax). BM=BN=64, 256 threads, 4x4/thread.
// Thread layout: qg = tid>>4 (4 q-rows), kg = tid&15 (4 k-cols / 4 d-cols).
// Row reductions via shfl butterflies over 16 consecutive lanes.
// grid = (S/64, B*H); dynamic smem 4 * 64*68 floats = 69632 B.
// ---------------------------------------------------------------------------
#define ATT_SMEM (4 * 64 * 68 * 4)

__global__ __launch_bounds__(256) void attn_kernel()
{
    extern __shared__ float sm[];
    float* Qs = sm;              // [64][68]  Qs[d][q]  (prescaled by 1/8)
    float* Ks = Qs + 64 * 68;    // [64][68]  Ks[d][k]
    float* Vs = Ks + 64 * 68;    // [64][68]  Vs[k][d]
    float* Ps = Vs + 64 * 68;    // [64][68]  Ps[k][q]

    const int bh = blockIdx.y;
    const int q0 = blockIdx.x * 64;
    const int tid = threadIdx.x;
    const int kg = tid & 15;     // k-group in QK, d-group in PV
    const int qg = tid >> 4;     // q-group (rows qg*4 .. qg*4+3)

    const float* Qg = g_Q + (size_t)bh * S_ * D_;
    const float* Kg = g_K + (size_t)bh * S_ * D_;
    const float* Vg = g_V + (size_t)bh * S_ * D_;

    // Load Q tile transposed, prescaled by 1/sqrt(D)=0.125
#pragma unroll
    for (int it = 0; it < 4; it++) {
        int i   = tid + it * 256;   // 0..1023 float4 slots
        int row = i >> 4;           // 0..63
        int c4  = (i & 15) * 4;     // 0..60
        float4 f = *(const float4*)(Qg + (size_t)(q0 + row) * D_ + c4);
        Qs[(c4 + 0) * 68 + row] = f.x * 0.125f;
        Qs[(c4 + 1) * 68 + row] = f.y * 0.125f;
        Qs[(c4 + 2) * 68 + row] = f.z * 0.125f;
        Qs[(c4 + 3) * 68 + row] = f.w * 0.125f;
    }

    float m_i[4], l_i[4], o[4][4];
#pragma unroll
    for (int i = 0; i < 4; i++) {
        m_i[i] = -1e30f;
        l_i[i] = 0.f;
#pragma unroll
        for (int j = 0; j < 4; j++) o[i][j] = 0.f;
    }

    for (int kb = 0; kb < S_; kb += 64) {
        // Load K (transposed) and V (natural) tiles
#pragma unroll
        for (int it = 0; it < 4; it++) {
            int i   = tid + it * 256;
            int row = i >> 4;
            int c4  = (i & 15) * 4;
            float4 f = *(const float4*)(Kg + (size_t)(kb + row) * D_ + c4);
            Ks[(c4 + 0) * 68 + row] = f.x;
            Ks[(c4 + 1) * 68 + row] = f.y;
            Ks[(c4 + 2) * 68 + row] = f.z;
            Ks[(c4 + 3) * 68 + row] = f.w;
            float4 g = *(const float4*)(Vg + (size_t)(kb + row) * D_ + c4);
            *(float4*)&Vs[row * 68 + c4] = g;
        }
        __syncthreads();

        // S = (Q/8) * K^T  : 4x4 per thread over d=0..63
        float s[4][4];
#pragma unroll
        for (int i = 0; i < 4; i++)
#pragma unroll
            for (int j = 0; j < 4; j++) s[i][j] = 0.f;

#pragma unroll 16
        for (int d = 0; d < 64; d++) {
            float4 qf = *(float4*)&Qs[d * 68 + qg * 4];
            float4 kf = *(float4*)&Ks[d * 68 + kg * 4];
            float aq[4] = {qf.x, qf.y, qf.z, qf.w};
            float ak[4] = {kf.x, kf.y, kf.z, kf.w};
#pragma unroll
            for (int i = 0; i < 4; i++)
#pragma unroll
                for (int j = 0; j < 4; j++) s[i][j] += aq[i] * ak[j];
        }

        // Online softmax per q-row (reduce across 16 kg lanes)
#pragma unroll
        for (int i = 0; i < 4; i++) {
            float tm = fmaxf(fmaxf(s[i][0], s[i][1]), fmaxf(s[i][2], s[i][3]));
#pragma unroll
            for (int off = 1; off < 16; off <<= 1)
                tm = fmaxf(tm, __shfl_xor_sync(0xffffffffu, tm, off));
            float mn = fmaxf(m_i[i], tm);
            float corr = __expf(m_i[i] - mn);
            m_i[i] = mn;
            float rs = 0.f;
#pragma unroll
            for (int j = 0; j < 4; j++) {
                float p = __expf(s[i][j] - mn);
                s[i][j] = p;
                rs += p;
            }
#pragma unroll
            for (int off = 1; off < 16; off <<= 1)
                rs += __shfl_xor_sync(0xffffffffu, rs, off);
            l_i[i] = l_i[i] * corr + rs;
#pragma unroll
            for (int j = 0; j < 4; j++) o[i][j] *= corr;
        }

        // Stage P transposed: Ps[k][q]
#pragma unroll
        for (int j = 0; j < 4; j++) {
            float4 pv = make_float4(s[0][j], s[1][j], s[2][j], s[3][j]);
            *(float4*)&Ps[(kg * 4 + j) * 68 + qg * 4] = pv;
        }
        __syncthreads();

        // O += P * V : 4x4 per thread over kk=0..63 (kg acts as d-group)
#pragma unroll 16
        for (int kk = 0; kk < 64; kk++) {
            float4 pf = *(float4*)&Ps[kk * 68 + qg * 4];
            float4 vf = *(float4*)&Vs[kk * 68 + kg * 4];
            float ap[4] = {pf.x, pf.y, pf.z, pf.w};
            float av[4] = {vf.x, vf.y, vf.z, vf.w};
#pragma unroll
            for (int i = 0; i < 4; i++)
#pragma unroll
                for (int j = 0; j < 4; j++) o[i][j] += ap[i] * av[j];
        }
        __syncthreads();
    }

    float* Cg = g_C + ((size_t)bh * S_ + q0) * D_;
#pragma unroll
    for (int i = 0; i < 4; i++) {
        float inv = 1.f / l_i[i];
        float4 r = make_float4(o[i][0] * inv, o[i][1] * inv, o[i][2] * inv, o[i][3] * inv);
        *(float4*)(Cg + (size_t)(qg * 4 + i) * D_ + kg * 4) = r;
    }
}

// ---------------------------------------------------------------------------
// Output projection: out[b,s,:] = ctx_row(b,s) @ Wo + bo
// ctx_row(b,s)[e] = g_C[b, e/64, s, e%64]  (head-concat gather in A load)
// Tile 128x64x16, grid = (B*S/128, E/64)
// ---------------------------------------------------------------------------
__global__ __launch_bounds__(256) void oproj_kernel(
    const float* __restrict__ Wo, const float* __restrict__ bo, float* __restrict__ out)
{
    __shared__ float As[16][132];
    __shared__ float Bs[16][64];

    const int m0 = blockIdx.x * 128;          // row in [0, B*S)
    const int n0 = blockIdx.y * 64;
    const int tid = threadIdx.x;
    const int ng = tid & 15;
    const int mg = tid >> 4;
    const int b = m0 >> 11;                   // S_=2048 rows per batch
    const int sbase = m0 & (S_ - 1);

    float acc[8][4];
#pragma unroll
    for (int i = 0; i < 8; i++)
#pragma unroll
        for (int j = 0; j < 4; j++) acc[i][j] = 0.f;

    for (int k0 = 0; k0 < E_; k0 += 16) {
#pragma unroll
        for (int it = 0; it < 2; it++) {
            int i   = tid + it * 256;
            int row = i >> 2;
            int c4  = (i & 3) * 4;
            int e = k0 + c4;
            int h = e >> 6;
            int dd = e & 63;
            float4 f = *(const float4*)(g_C +
                (((size_t)(b * H_ + h) * S_ + sbase + row) * D_ + dd));
            As[c4 + 0][row] = f.x; As[c4 + 1][row] = f.y;
            As[c4 + 2][row] = f.z; As[c4 + 3][row] = f.w;
        }
        {
            int r  = tid >> 4;
            int c4 = (tid & 15) * 4;
            *(float4*)&Bs[r][c4] = *(const float4*)(Wo + (size_t)(k0 + r) * E_ + n0 + c4);
        }
        __syncthreads();
#pragma unroll
        for (int kk = 0; kk < 16; kk++) {
            float4 a0 = *(float4*)&As[kk][mg * 8];
            float4 a1 = *(float4*)&As[kk][mg * 8 + 4];
            float4 b4 = *(float4*)&Bs[kk][ng * 4];
            float a[8] = {a0.x, a0.y, a0.z, a0.w, a1.x, a1.y, a1.z, a1.w};
            float bb[4] = {b4.x, b4.y, b4.z, b4.w};
#pragma unroll
            for (int i = 0; i < 8; i++)
#pragma unroll
                for (int j = 0; j < 4; j++) acc[i][j] += a[i] * bb[j];
        }
        __syncthreads();
    }

    float4 b4 = *(const float4*)(bo + n0 + ng * 4);
#pragma unroll
    for (int i = 0; i < 8; i++) {
        size_t row = (size_t)m0 + mg * 8 + i;
        float4 r;
        r.x = acc[i][0] + b4.x; r.y = acc[i][1] + b4.y;
        r.z = acc[i][2] + b4.z; r.w = acc[i][3] + b4.w;
        *(float4*)(out + row * E_ + n0 + ng * 4) = r;
    }
}

// ---------------------------------------------------------------------------
extern "C" void kernel_launch(void* const* d_in, const int* in_sizes, int n_in,
                              void* d_out, int out_size)
{
    const float* q  = (const float*)d_in[0];
    const float* k  = (const float*)d_in[1];
    const float* v  = (const float*)d_in[2];
    const float* Wq = (const float*)d_in[3];
    const float* Wk = (const float*)d_in[4];
    const float* Wv = (const float*)d_in[5];
    const float* bq = (const float*)d_in[6];
    const float* bk = (const float*)d_in[7];
    const float* bv = (const float*)d_in[8];
    const float* Wo = (const float*)d_in[9];
    const float* bo = (const float*)d_in[10];
    float* out = (float*)d_out;

    cudaFuncSetAttribute(attn_kernel, cudaFuncAttributeMaxDynamicSharedMemorySize, ATT_SMEM);

    proj_kernel<<<dim3(S_ / 128, BH_, 3), 256>>>(q, k, v, Wq, Wk, Wv, bq, bk, bv);
    attn_kernel<<<dim3(S_ / 64, BH_), 256, ATT_SMEM>>>();
    oproj_kernel<<<dim3((B_ * S_) / 128, E_ / 64), 256>>>(Wo, bo, out);
}

// round 2
// speedup vs baseline: 1.6286x; 1.6286x over previous
#include <cuda_runtime.h>
#include <math.h>

#define B_ 2
#define S_ 2048
#define E_ 1024
#define H_ 16
#define D_ 64
#define BH_ (B_*H_)

// Scratch (allocation-free rule: device globals)
__device__ float g_Q[(size_t)BH_ * S_ * D_];
__device__ float g_K[(size_t)BH_ * S_ * D_];
__device__ float g_V[(size_t)BH_ * S_ * D_];
__device__ float g_C[(size_t)BH_ * S_ * D_];

// ---------------------------------------------------------------------------
// QKV projection: Out[b,h,s,d] = sum_e X[b,s,e] * W[h,e,d] + bias[h,d]
// GEMM tile 128(M=s) x 64(N=d full) x 16(K=e chunk), 256 threads, 8x4/thread.
// grid = (S/128, B*H, 3)  z: 0=q,1=k,2=v
// ---------------------------------------------------------------------------
__global__ __launch_bounds__(256) void proj_kernel(
    const float* __restrict__ q, const float* __restrict__ k, const float* __restrict__ v,
    const float* __restrict__ Wq, const float* __restrict__ Wk, const float* __restrict__ Wv,
    const float* __restrict__ bq, const float* __restrict__ bk, const float* __restrict__ bv)
{
    __shared__ float As[16][132];   // A transposed: As[kk][m], padded stride 132
    __shared__ float Bs[16][64];    // Bs[kk][n]

    const int z = blockIdx.z;
    const float* X    = (z == 0) ? q  : (z == 1) ? k  : v;
    const float* W    = (z == 0) ? Wq : (z == 1) ? Wk : Wv;
    const float* bias = (z == 0) ? bq : (z == 1) ? bk : bv;
    float* Out        = (z == 0) ? g_Q : (z == 1) ? g_K : g_V;

    const int bh = blockIdx.y;
    const int b = bh >> 4;
    const int h = bh & 15;
    const int s0 = blockIdx.x * 128;
    const int tid = threadIdx.x;
    const int ng = tid & 15;   // n-group: 4 cols
    const int mg = tid >> 4;   // m-group: 8 rows

    const float* Xb = X + ((size_t)b * S_ + s0) * E_;
    const float* Wh = W + (size_t)h * E_ * D_;

    float acc[8][4];
#pragma unroll
    for (int i = 0; i < 8; i++)
#pragma unroll
        for (int j = 0; j < 4; j++) acc[i][j] = 0.f;

    for (int k0 = 0; k0 < E_; k0 += 16) {
        // load A tile 128x16, store transposed
#pragma unroll
        for (int it = 0; it < 2; it++) {
            int i   = tid + it * 256;       // 0..511 float4 slots
            int row = i >> 2;               // 0..127
            int c4  = (i & 3) * 4;          // 0,4,8,12
            float4 f = *(const float4*)(Xb + (size_t)row * E_ + k0 + c4);
            As[c4 + 0][row] = f.x; As[c4 + 1][row] = f.y;
            As[c4 + 2][row] = f.z; As[c4 + 3][row] = f.w;
        }
        // load B tile 16x64
        {
            int r  = tid >> 4;
            int c4 = (tid & 15) * 4;
            *(float4*)&Bs[r][c4] = *(const float4*)(Wh + (size_t)(k0 + r) * D_ + c4);
        }
        __syncthreads();
#pragma unroll
        for (int kk = 0; kk < 16; kk++) {
            float4 a0 = *(float4*)&As[kk][mg * 8];
            float4 a1 = *(float4*)&As[kk][mg * 8 + 4];
            float4 b4 = *(float4*)&Bs[kk][ng * 4];
            float a[8] = {a0.x, a0.y, a0.z, a0.w, a1.x, a1.y, a1.z, a1.w};
            float bb[4] = {b4.x, b4.y, b4.z, b4.w};
#pragma unroll
            for (int i = 0; i < 8; i++)
#pragma unroll
                for (int j = 0; j < 4; j++) acc[i][j] += a[i] * bb[j];
        }
        __syncthreads();
    }

    float4 bias4 = *(const float4*)(bias + h * D_ + ng * 4);
    float* Ob = Out + ((size_t)bh * S_ + s0 + mg * 8) * D_ + ng * 4;
#pragma unroll
    for (int i = 0; i < 8; i++) {
        float4 r;
        r.x = acc[i][0] + bias4.x; r.y = acc[i][1] + bias4.y;
        r.z = acc[i][2] + bias4.z; r.w = acc[i][3] + bias4.w;
        *(float4*)(Ob + (size_t)i * D_) = r;
    }
}

// ---------------------------------------------------------------------------
// Flash attention (fp32, online softmax). BM=BN=64, 256 threads, 4x4/thread.
// Thread layout: qg = tid>>4 (4 q-rows), kg = tid&15 (4 k-cols / 4 d-cols).
// Row reductions via shfl butterflies over 16 consecutive lanes.
// grid = (S/64, B*H); dynamic smem 4 * 64*68 floats = 69632 B.
// ---------------------------------------------------------------------------
#define ATT_SMEM (4 * 64 * 68 * 4)

__global__ __launch_bounds__(256) void attn_kernel()
{
    extern __shared__ float sm[];
    float* Qs = sm;              // [64][68]  Qs[d][q]  (prescaled by 1/8)
    float* Ks = Qs + 64 * 68;    // [64][68]  Ks[d][k]
    float* Vs = Ks + 64 * 68;    // [64][68]  Vs[k][d]
    float* Ps = Vs + 64 * 68;    // [64][68]  Ps[k][q]

    const int bh = blockIdx.y;
    const int q0 = blockIdx.x * 64;
    const int tid = threadIdx.x;
    const int kg = tid & 15;     // k-group in QK, d-group in PV
    const int qg = tid >> 4;     // q-group (rows qg*4 .. qg*4+3)

    const float* Qg = g_Q + (size_t)bh * S_ * D_;
    const float* Kg = g_K + (size_t)bh * S_ * D_;
    const float* Vg = g_V + (size_t)bh * S_ * D_;

    // Load Q tile transposed, prescaled by 1/sqrt(D)=0.125
#pragma unroll
    for (int it = 0; it < 4; it++) {
        int i   = tid + it * 256;   // 0..1023 float4 slots
        int row = i >> 4;           // 0..63
        int c4  = (i & 15) * 4;     // 0..60
        float4 f = *(const float4*)(Qg + (size_t)(q0 + row) * D_ + c4);
        Qs[(c4 + 0) * 68 + row] = f.x * 0.125f;
        Qs[(c4 + 1) * 68 + row] = f.y * 0.125f;
        Qs[(c4 + 2) * 68 + row] = f.z * 0.125f;
        Qs[(c4 + 3) * 68 + row] = f.w * 0.125f;
    }

    float m_i[4], l_i[4], o[4][4];
#pragma unroll
    for (int i = 0; i < 4; i++) {
        m_i[i] = -1e30f;
        l_i[i] = 0.f;
#pragma unroll
        for (int j = 0; j < 4; j++) o[i][j] = 0.f;
    }

    for (int kb = 0; kb < S_; kb += 64) {
        // Load K (transposed) and V (natural) tiles
#pragma unroll
        for (int it = 0; it < 4; it++) {
            int i   = tid + it * 256;
            int row = i >> 4;
            int c4  = (i & 15) * 4;
            float4 f = *(const float4*)(Kg + (size_t)(kb + row) * D_ + c4);
            Ks[(c4 + 0) * 68 + row] = f.x;
            Ks[(c4 + 1) * 68 + row] = f.y;
            Ks[(c4 + 2) * 68 + row] = f.z;
            Ks[(c4 + 3) * 68 + row] = f.w;
            float4 g = *(const float4*)(Vg + (size_t)(kb + row) * D_ + c4);
            *(float4*)&Vs[row * 68 + c4] = g;
        }
        __syncthreads();

        // S = (Q/8) * K^T  : 4x4 per thread over d=0..63
        float s[4][4];
#pragma unroll
        for (int i = 0; i < 4; i++)
#pragma unroll
            for (int j = 0; j < 4; j++) s[i][j] = 0.f;

#pragma unroll 16
        for (int d = 0; d < 64; d++) {
            float4 qf = *(float4*)&Qs[d * 68 + qg * 4];
            float4 kf = *(float4*)&Ks[d * 68 + kg * 4];
            float aq[4] = {qf.x, qf.y, qf.z, qf.w};
            float ak[4] = {kf.x, kf.y, kf.z, kf.w};
#pragma unroll
            for (int i = 0; i < 4; i++)
#pragma unroll
                for (int j = 0; j < 4; j++) s[i][j] += aq[i] * ak[j];
        }

        // Online softmax per q-row (reduce across 16 kg lanes)
#pragma unroll
        for (int i = 0; i < 4; i++) {
            float tm = fmaxf(fmaxf(s[i][0], s[i][1]), fmaxf(s[i][2], s[i][3]));
#pragma unroll
            for (int off = 1; off < 16; off <<= 1)
                tm = fmaxf(tm, __shfl_xor_sync(0xffffffffu, tm, off));
            float mn = fmaxf(m_i[i], tm);
            float corr = __expf(m_i[i] - mn);
            m_i[i] = mn;
            float rs = 0.f;
#pragma unroll
            for (int j = 0; j < 4; j++) {
                float p = __expf(s[i][j] - mn);
                s[i][j] = p;
                rs += p;
            }
#pragma unroll
            for (int off = 1; off < 16; off <<= 1)
                rs += __shfl_xor_sync(0xffffffffu, rs, off);
            l_i[i] = l_i[i] * corr + rs;
#pragma unroll
            for (int j = 0; j < 4; j++) o[i][j] *= corr;
        }

        // Stage P transposed: Ps[k][q]
#pragma unroll
        for (int j = 0; j < 4; j++) {
            float4 pv = make_float4(s[0][j], s[1][j], s[2][j], s[3][j]);
            *(float4*)&Ps[(kg * 4 + j) * 68 + qg * 4] = pv;
        }
        __syncthreads();

        // O += P * V : 4x4 per thread over kk=0..63 (kg acts as d-group)
#pragma unroll 16
        for (int kk = 0; kk < 64; kk++) {
            float4 pf = *(float4*)&Ps[kk * 68 + qg * 4];
            float4 vf = *(float4*)&Vs[kk * 68 + kg * 4];
            float ap[4] = {pf.x, pf.y, pf.z, pf.w};
            float av[4] = {vf.x, vf.y, vf.z, vf.w};
#pragma unroll
            for (int i = 0; i < 4; i++)
#pragma unroll
                for (int j = 0; j < 4; j++) o[i][j] += ap[i] * av[j];
        }
        __syncthreads();
    }

    float* Cg = g_C + ((size_t)bh * S_ + q0) * D_;
#pragma unroll
    for (int i = 0; i < 4; i++) {
        float inv = 1.f / l_i[i];
        float4 r = make_float4(o[i][0] * inv, o[i][1] * inv, o[i][2] * inv, o[i][3] * inv);
        *(float4*)(Cg + (size_t)(qg * 4 + i) * D_ + kg * 4) = r;
    }
}

// ---------------------------------------------------------------------------
// Output projection: out[b,s,:] = ctx_row(b,s) @ Wo + bo
// ctx_row(b,s)[e] = g_C[b, e/64, s, e%64]  (head-concat gather in A load)
// Tile 128x64x16, grid = (B*S/128, E/64)
// ---------------------------------------------------------------------------
__global__ __launch_bounds__(256) void oproj_kernel(
    const float* __restrict__ Wo, const float* __restrict__ bo, float* __restrict__ out)
{
    __shared__ float As[16][132];
    __shared__ float Bs[16][64];

    const int m0 = blockIdx.x * 128;          // row in [0, B*S)
    const int n0 = blockIdx.y * 64;
    const int tid = threadIdx.x;
    const int ng = tid & 15;
    const int mg = tid >> 4;
    const int b = m0 >> 11;                   // S_=2048 rows per batch
    const int sbase = m0 & (S_ - 1);

    float acc[8][4];
#pragma unroll
    for (int i = 0; i < 8; i++)
#pragma unroll
        for (int j = 0; j < 4; j++) acc[i][j] = 0.f;

    for (int k0 = 0; k0 < E_; k0 += 16) {
#pragma unroll
        for (int it = 0; it < 2; it++) {
            int i   = tid + it * 256;
            int row = i >> 2;
            int c4  = (i & 3) * 4;
            int e = k0 + c4;
            int h = e >> 6;
            int dd = e & 63;
            float4 f = *(const float4*)(g_C +
                (((size_t)(b * H_ + h) * S_ + sbase + row) * D_ + dd));
            As[c4 + 0][row] = f.x; As[c4 + 1][row] = f.y;
            As[c4 + 2][row] = f.z; As[c4 + 3][row] = f.w;
        }
        {
            int r  = tid >> 4;
            int c4 = (tid & 15) * 4;
            *(float4*)&Bs[r][c4] = *(const float4*)(Wo + (size_t)(k0 + r) * E_ + n0 + c4);
        }
        __syncthreads();
#pragma unroll
        for (int kk = 0; kk < 16; kk++) {
            float4 a0 = *(float4*)&As[kk][mg * 8];
            float4 a1 = *(float4*)&As[kk][mg * 8 + 4];
            float4 b4 = *(float4*)&Bs[kk][ng * 4];
            float a[8] = {a0.x, a0.y, a0.z, a0.w, a1.x, a1.y, a1.z, a1.w};
            float bb[4] = {b4.x, b4.y, b4.z, b4.w};
#pragma unroll
            for (int i = 0; i < 8; i++)
#pragma unroll
                for (int j = 0; j < 4; j++) acc[i][j] += a[i] * bb[j];
        }
        __syncthreads();
    }

    float4 b4 = *(const float4*)(bo + n0 + ng * 4);
#pragma unroll
    for (int i = 0; i < 8; i++) {
        size_t row = (size_t)m0 + mg * 8 + i;
        float4 r;
        r.x = acc[i][0] + b4.x; r.y = acc[i][1] + b4.y;
        r.z = acc[i][2] + b4.z; r.w = acc[i][3] + b4.w;
        *(float4*)(out + row * E_ + n0 + ng * 4) = r;
    }
}

// ---------------------------------------------------------------------------
extern "C" void kernel_launch(void* const* d_in, const int* in_sizes, int n_in,
                              void* d_out, int out_size)
{
    const float* q  = (const float*)d_in[0];
    const float* k  = (const float*)d_in[1];
    const float* v  = (const float*)d_in[2];
    const float* Wq = (const float*)d_in[3];
    const float* Wk = (const float*)d_in[4];
    const float* Wv = (const float*)d_in[5];
    const float* bq = (const float*)d_in[6];
    const float* bk = (const float*)d_in[7];
    const float* bv = (const float*)d_in[8];
    const float* Wo = (const float*)d_in[9];
    const float* bo = (const float*)d_in[10];
    float* out = (float*)d_out;

    cudaFuncSetAttribute(attn_kernel, cudaFuncAttributeMaxDynamicSharedMemorySize, ATT_SMEM);

    proj_kernel<<<dim3(S_ / 128, BH_, 3), 256>>>(q, k, v, Wq, Wk, Wv, bq, bk, bv);
    attn_kernel<<<dim3(S_ / 64, BH_), 256, ATT_SMEM>>>();
    oproj_kernel<<<dim3((B_ * S_) / 128, E_ / 64), 256>>>(Wo, bo, out);
}